// round 14
// baseline (speedup 1.0000x reference)
#include <cuda_runtime.h>
#include <cuda_bf16.h>
#include <math.h>
#include <stdint.h>

#define N_NODES 65536
#define DIM     128
#define GR      128
#define NE      262144
#define GSTEPS  6

// ---------------- scratch ----------------
__device__ float g_H  [N_NODES * DIM];
__device__ float g_M  [N_NODES * DIM];
__device__ float g_AGG[N_NODES * DIM];
__device__ float g_GX [N_NODES * 384];
__device__ float g_GH [N_NODES * 384];
__device__ float g_WT [GSTEPS * DIM * DIM];
__device__ float g_T1 [128 * GR * 512];      // stride 512; l>=510 garbage (masked)
__device__ float g_U1 [256 * GR * 512];
__device__ float g_T2 [128 * GR * 254];
__device__ float g_U2 [256 * GR * 254];
__device__ float g_P2 [128 * GR * 127];
__device__ float g_Q2 [256 * GR * 127];
__device__ float g_MEAN[256];
__device__ float g_RSTD[256];
// bf16 split operands
__device__ __nv_bfloat16 g_Hhi [N_NODES * DIM];
__device__ __nv_bfloat16 g_Hlo [N_NODES * DIM];
__device__ __nv_bfloat16 g_Ahi [N_NODES * DIM];
__device__ __nv_bfloat16 g_Alo [N_NODES * DIM];
__device__ __nv_bfloat16 g_WThi[GSTEPS * DIM * DIM];
__device__ __nv_bfloat16 g_WTlo[GSTEPS * DIM * DIM];
__device__ __nv_bfloat16 g_IHhi[384 * DIM];
__device__ __nv_bfloat16 g_IHlo[384 * DIM];
__device__ __nv_bfloat16 g_HHhi[384 * DIM];
__device__ __nv_bfloat16 g_HHlo[384 * DIM];
__device__ __nv_bfloat16 g_CAThi[256 * N_NODES + 256];
__device__ __nv_bfloat16 g_CATlo[256 * N_NODES + 256];
__device__ __nv_bfloat16 g_P1hi[128 * GR * 254 + 256];
__device__ __nv_bfloat16 g_P1lo[128 * GR * 254 + 256];
__device__ __nv_bfloat16 g_Q1hi[256 * GR * 254 + 256];
__device__ __nv_bfloat16 g_Q1lo[256 * GR * 254 + 256];
// conv weights reordered [t][co][ci], split
__device__ __nv_bfloat16 g_CW1hi[3 * 128 * 128], g_CW1lo[3 * 128 * 128];
__device__ __nv_bfloat16 g_CW2hi[128 * 128],     g_CW2lo[128 * 128];
__device__ __nv_bfloat16 g_CC1hi[3 * 256 * 256], g_CC1lo[3 * 256 * 256];
__device__ __nv_bfloat16 g_CC2hi[256 * 256],     g_CC2lo[256 * 256];

__device__ __forceinline__ uint32_t smem_u32(const void* p) {
    uint32_t a;
    asm("{ .reg .u64 t; cvta.to.shared.u64 t, %1; cvt.u32.u64 %0, t; }" : "=r"(a) : "l"(p));
    return a;
}

#define ROWB 272
#define TILEB (128 * ROWB)

// ---- one split-product pass: acc += A(ab) * B(bb)^T over K=128 ----
__device__ __forceinline__ void mma_product(
    uint32_t ab, uint32_t bb, float (*acc)[4][4],
    uint32_t a_r, uint32_t a_k, uint32_t b_r, uint32_t b_k)
{
#pragma unroll
    for (int ks = 0; ks < 8; ks++) {
        uint32_t a[4][4], b[4][2];
#pragma unroll
        for (int mi = 0; mi < 4; mi++) {
            const uint32_t addr = ab + (a_r + mi * 16) * ROWB + (ks * 16 + a_k) * 2;
            asm volatile("ldmatrix.sync.aligned.m8n8.x4.shared.b16 {%0,%1,%2,%3}, [%4];"
                         : "=r"(a[mi][0]), "=r"(a[mi][1]), "=r"(a[mi][2]), "=r"(a[mi][3])
                         : "r"(addr));
        }
#pragma unroll
        for (int ni = 0; ni < 4; ni++) {
            const uint32_t addr = bb + (b_r + ni * 8) * ROWB + (ks * 16 + b_k) * 2;
            asm volatile("ldmatrix.sync.aligned.m8n8.x2.shared.b16 {%0,%1}, [%2];"
                         : "=r"(b[ni][0]), "=r"(b[ni][1]) : "r"(addr));
        }
#pragma unroll
        for (int mi = 0; mi < 4; mi++)
#pragma unroll
            for (int ni = 0; ni < 4; ni++) {
                asm volatile(
                    "mma.sync.aligned.m16n8k16.row.col.f32.bf16.bf16.f32 "
                    "{%0,%1,%2,%3}, {%4,%5,%6,%7}, {%8,%9}, {%0,%1,%2,%3};"
                    : "+f"(acc[mi][ni][0]), "+f"(acc[mi][ni][1]),
                      "+f"(acc[mi][ni][2]), "+f"(acc[mi][ni][3])
                    : "r"(a[mi][0]), "r"(a[mi][1]), "r"(a[mi][2]), "r"(a[mi][3]),
                      "r"(b[ni][0]), "r"(b[ni][1]));
            }
    }
}

// ================= split-bf16 GEMM, 3 resident tiles, 2 CTAs/SM =================
#define G_A0 0
#define G_A1 TILEB
#define G_B  (2 * TILEB)
#define MMA_SMEM (3 * TILEB)     // 104448 B

__global__ __launch_bounds__(256, 2) void gemm_mma(
    const __nv_bfloat16* __restrict__ Ahi, const __nv_bfloat16* __restrict__ Alo,
    const __nv_bfloat16* __restrict__ Bhi, const __nv_bfloat16* __restrict__ Blo,
    const float* __restrict__ bias, float* __restrict__ C, int Ncols)
{
    extern __shared__ char sm[];
    const uint32_t sb = smem_u32(sm);
    const int tid  = threadIdx.x;
    const int wid  = tid >> 5;
    const int lane = tid & 31;

    const int r   = tid & 127;
    const int kc  = (tid >> 7) << 6;
    const size_t ar = ((size_t)blockIdx.x * 128 + r) * 128 + kc;
    const size_t br = ((size_t)blockIdx.y * 128 + r) * 128 + kc;
    char* dst = sm + r * ROWB + kc * 2;

#pragma unroll
    for (int kk = 0; kk < 64; kk += 8) {
        *(uint4*)(dst + G_A0 + kk * 2) = *(const uint4*)(Ahi + ar + kk);
        *(uint4*)(dst + G_A1 + kk * 2) = *(const uint4*)(Alo + ar + kk);
        *(uint4*)(dst + G_B  + kk * 2) = *(const uint4*)(Bhi + br + kk);
    }
    __syncthreads();

    const int warpM = (wid >> 2) * 64;
    const int warpN = (wid & 3) * 32;
    const uint32_t a_r = warpM + (lane & 15);
    const uint32_t a_k = (lane >> 4) * 8;
    const uint32_t b_r = warpN + (lane & 7);
    const uint32_t b_k = ((lane >> 3) & 1) * 8;

    float acc[4][4][4];
#pragma unroll
    for (int i = 0; i < 4; i++)
#pragma unroll
        for (int j = 0; j < 4; j++)
#pragma unroll
            for (int k = 0; k < 4; k++) acc[i][j][k] = 0.f;

    mma_product(sb + G_A0, sb + G_B, acc, a_r, a_k, b_r, b_k);   // Ahi*Bhi
    mma_product(sb + G_A1, sb + G_B, acc, a_r, a_k, b_r, b_k);   // Alo*Bhi
    __syncthreads();
#pragma unroll
    for (int kk = 0; kk < 64; kk += 8)
        *(uint4*)(dst + G_B + kk * 2) = *(const uint4*)(Blo + br + kk);
    __syncthreads();
    mma_product(sb + G_A0, sb + G_B, acc, a_r, a_k, b_r, b_k);   // Ahi*Blo

    const int rbase = blockIdx.x * 128 + warpM + (lane >> 2);
    const int cbase = blockIdx.y * 128 + warpN + 2 * (lane & 3);
#pragma unroll
    for (int mi = 0; mi < 4; mi++) {
#pragma unroll
        for (int ni = 0; ni < 4; ni++) {
            const int row = rbase + mi * 16;
            const int col = cbase + ni * 8;
            float b0 = 0.f, b1 = 0.f;
            if (bias) { b0 = bias[col]; b1 = bias[col + 1]; }
            *(float2*)(C + (size_t)row * Ncols + col) =
                make_float2(acc[mi][ni][0] + b0, acc[mi][ni][1] + b1);
            *(float2*)(C + (size_t)(row + 8) * Ncols + col) =
                make_float2(acc[mi][ni][2] + b0, acc[mi][ni][3] + b1);
        }
    }
}

// ================= conv as split-bf16 mma GEMM, 3 resident tiles =================
#define CB_ROWS 130
#define CBTILE (CB_ROWS * ROWB)
#define C_A0 0
#define C_A1 TILEB
#define C_B  (2 * TILEB)
#define CONV_SMEM (2 * TILEB + CBTILE)     // 104992 B

__global__ __launch_bounds__(256, 2) void conv_mma(
    const __nv_bfloat16* __restrict__ Whi, const __nv_bfloat16* __restrict__ Wlo,
    const __nv_bfloat16* __restrict__ Xhi, const __nv_bfloat16* __restrict__ Xlo,
    const float* __restrict__ bias, float* __restrict__ C,
    int Cout, int Cin, int KW, int NS)
{
    extern __shared__ char sm[];
    const uint32_t sb = smem_u32(sm);
    const int tid  = threadIdx.x;
    const int wid  = tid >> 5;
    const int lane = tid & 31;
    const int n0   = blockIdx.x * 128;
    const int cob  = blockIdx.y * 128;

    const int warpM = (wid >> 2) * 64;
    const int warpN = (wid & 3) * 32;
    const uint32_t a_r = warpM + (lane & 15);
    const uint32_t a_k = (lane >> 4) * 8;
    const uint32_t b_r = warpN + (lane & 7);
    const uint32_t b_k = ((lane >> 3) & 1) * 8;

    float acc[4][4][4];
#pragma unroll
    for (int i = 0; i < 4; i++)
#pragma unroll
        for (int j = 0; j < 4; j++)
#pragma unroll
            for (int k = 0; k < 4; k++) acc[i][j][k] = 0.f;

    const int nkc = Cin >> 7;
    for (int kc = 0; kc < nkc; kc++) {
        const int ci0 = kc << 7;

        // ======== pass 1: B = Xhi ========
        __syncthreads();
        {
            const int nn  = tid & 127;
            const int kst = tid >> 7;
            const __nv_bfloat16* ph = Xhi + (size_t)(ci0 + kst) * NS + n0 + nn;
            char* dh = sm + C_B + nn * ROWB + kst * 2;
#pragma unroll 8
            for (int j = 0; j < 64; j++) {
                *(__nv_bfloat16*)dh = *ph;
                ph += 2 * (size_t)NS; dh += 4;
            }
            const int k2 = tid & 127;
            const int re = 128 + (tid >> 7);
            *(__nv_bfloat16*)(sm + C_B + re * ROWB + k2 * 2) = Xhi[(size_t)(ci0 + k2) * NS + n0 + re];
        }
        for (int t = 0; t < KW; t++) {
            __syncthreads();
            {   // stage A hi + lo for this tap
                const int r  = tid & 127;
                const int kh = (tid >> 7) << 6;
                const size_t src = ((size_t)(t * Cout + cob + r)) * Cin + ci0 + kh;
                char* da = sm + C_A0 + r * ROWB + kh * 2;
                char* dl = sm + C_A1 + r * ROWB + kh * 2;
#pragma unroll
                for (int kk = 0; kk < 64; kk += 8) {
                    *(uint4*)(da + kk * 2) = *(const uint4*)(Whi + src + kk);
                    *(uint4*)(dl + kk * 2) = *(const uint4*)(Wlo + src + kk);
                }
            }
            __syncthreads();
            const uint32_t bb = sb + C_B + (uint32_t)t * ROWB;
            mma_product(sb + C_A0, bb, acc, a_r, a_k, b_r, b_k);  // Ahi*Bhi
            mma_product(sb + C_A1, bb, acc, a_r, a_k, b_r, b_k);  // Alo*Bhi
        }

        // ======== pass 2: B = Xlo (only Ahi) ========
        __syncthreads();
        {
            const int nn  = tid & 127;
            const int kst = tid >> 7;
            const __nv_bfloat16* pl = Xlo + (size_t)(ci0 + kst) * NS + n0 + nn;
            char* dl = sm + C_B + nn * ROWB + kst * 2;
#pragma unroll 8
            for (int j = 0; j < 64; j++) {
                *(__nv_bfloat16*)dl = *pl;
                pl += 2 * (size_t)NS; dl += 4;
            }
            const int k2 = tid & 127;
            const int re = 128 + (tid >> 7);
            *(__nv_bfloat16*)(sm + C_B + re * ROWB + k2 * 2) = Xlo[(size_t)(ci0 + k2) * NS + n0 + re];
        }
        for (int t = 0; t < KW; t++) {
            __syncthreads();
            {   // stage A hi for this tap
                const int r  = tid & 127;
                const int kh = (tid >> 7) << 6;
                const size_t src = ((size_t)(t * Cout + cob + r)) * Cin + ci0 + kh;
                char* da = sm + C_A0 + r * ROWB + kh * 2;
#pragma unroll
                for (int kk = 0; kk < 64; kk += 8)
                    *(uint4*)(da + kk * 2) = *(const uint4*)(Whi + src + kk);
            }
            __syncthreads();
            mma_product(sb + C_A0, sb + C_B + (uint32_t)t * ROWB, acc, a_r, a_k, b_r, b_k);
        }
    }

    const int rb  = cob + warpM + (lane >> 2);
    const int cb2 = n0 + warpN + 2 * (lane & 3);
#pragma unroll
    for (int mi = 0; mi < 4; mi++) {
#pragma unroll
        for (int ni = 0; ni < 4; ni++) {
            const int row = rb + mi * 16;
            const int col = cb2 + ni * 8;
            const float b0 = bias[row];
            const float b1 = bias[row + 8];
            *(float2*)(C + (size_t)row * NS + col) =
                make_float2(acc[mi][ni][0] + b0, acc[mi][ni][1] + b0);
            *(float2*)(C + (size_t)(row + 8) * NS + col) =
                make_float2(acc[mi][ni][2] + b1, acc[mi][ni][3] + b1);
        }
    }
}

// ---------------- fp32 -> (bf16 hi, bf16 lo) split ----------------
__global__ void split_kernel(const float* __restrict__ X, __nv_bfloat16* __restrict__ hi,
                             __nv_bfloat16* __restrict__ lo, int n4)
{
    const int i = blockIdx.x * 256 + threadIdx.x;
    if (i >= n4) return;
    const float4 v = ((const float4*)X)[i];
    float fs[4] = {v.x, v.y, v.z, v.w};
    __nv_bfloat16 hb[4], lb[4];
#pragma unroll
    for (int j = 0; j < 4; j++) {
        hb[j] = __float2bfloat16(fs[j]);
        lb[j] = __float2bfloat16(fs[j] - __bfloat162float(hb[j]));
    }
    ((uint2*)hi)[i] = *(uint2*)hb;
    ((uint2*)lo)[i] = *(uint2*)lb;
}

// ---------------- conv weight reorder+split ----------------
__global__ void convw_prep(const float* __restrict__ w, __nv_bfloat16* __restrict__ hi,
                           __nv_bfloat16* __restrict__ lo, int Cout, int Cin, int KW)
{
    const int idx = blockIdx.x * 256 + threadIdx.x;
    if (idx >= KW * Cout * Cin) return;
    const int ci = idx % Cin;
    const int co = (idx / Cin) % Cout;
    const int t  = idx / (Cin * Cout);
    const float v = w[((size_t)co * Cin + ci) * KW + t];
    const __nv_bfloat16 h = __float2bfloat16(v);
    hi[idx] = h;
    lo[idx] = __float2bfloat16(v - __bfloat162float(h));
}

// ---------------- edge scatter (vector RED) ----------------
__global__ void scatter_kernel(const float* __restrict__ Msg, const int* __restrict__ ei,
                               const float* __restrict__ ew, float* __restrict__ AGG)
{
    const int t = blockIdx.x * blockDim.x + threadIdx.x;
    const int e = t >> 5;
    const int j = (t & 31) << 2;
    const int s = ei[e];
    const int d = ei[NE + e];
    const float w = ew[e];
    const float4 v = *(const float4*)(Msg + (size_t)s * DIM + j);
    float* b = AGG + (size_t)d * DIM + j;
    asm volatile("red.global.add.v4.f32 [%0], {%1, %2, %3, %4};"
                 :: "l"(b), "f"(v.x * w), "f"(v.y * w), "f"(v.z * w), "f"(v.w * w)
                 : "memory");
}

__device__ __forceinline__ float fast_sigmoid(float v)
{
    v = fminf(fmaxf(v, -30.f), 30.f);
    return 1.f / (1.f + __expf(-v));
}
__device__ __forceinline__ float fast_tanh(float v)
{
    v = fminf(fmaxf(v, -15.f), 15.f);
    const float e = __expf(-2.f * v);
    return (1.f - e) / (1.f + e);
}

// ---------------- GRU update, fused bf16 split output ----------------
__global__ void gru_kernel(const float* __restrict__ GX, const float* __restrict__ GH,
                           float* __restrict__ H, __nv_bfloat16* __restrict__ Hhi,
                           __nv_bfloat16* __restrict__ Hlo)
{
    const int t = blockIdx.x * blockDim.x + threadIdx.x;
    const int i = t >> 5;
    const int j = (t & 31) << 2;
    const float* px = GX + (size_t)i * 384 + j;
    const float* ph = GH + (size_t)i * 384 + j;
    const float4 xr = *(const float4*)(px);
    const float4 xz = *(const float4*)(px + 128);
    const float4 xn = *(const float4*)(px + 256);
    const float4 hr = *(const float4*)(ph);
    const float4 hz = *(const float4*)(ph + 128);
    const float4 hn = *(const float4*)(ph + 256);
    float4* hp = (float4*)(H + (size_t)i * 128 + j);
    float4 h = *hp;
    float4 o;
    { const float r = fast_sigmoid(xr.x + hr.x), z = fast_sigmoid(xz.x + hz.x);
      const float n = fast_tanh(xn.x + r * hn.x); o.x = (1.f - z) * n + z * h.x; }
    { const float r = fast_sigmoid(xr.y + hr.y), z = fast_sigmoid(xz.y + hz.y);
      const float n = fast_tanh(xn.y + r * hn.y); o.y = (1.f - z) * n + z * h.y; }
    { const float r = fast_sigmoid(xr.z + hr.z), z = fast_sigmoid(xz.z + hz.z);
      const float n = fast_tanh(xn.z + r * hn.z); o.z = (1.f - z) * n + z * h.z; }
    { const float r = fast_sigmoid(xr.w + hr.w), z = fast_sigmoid(xz.w + hz.w);
      const float n = fast_tanh(xn.w + r * hn.w); o.w = (1.f - z) * n + z * h.w; }
    *hp = o;
    float fs[4] = {o.x, o.y, o.z, o.w};
    __nv_bfloat16 hb[4], lb[4];
#pragma unroll
    for (int q = 0; q < 4; q++) {
        hb[q] = __float2bfloat16(fs[q]);
        lb[q] = __float2bfloat16(fs[q] - __bfloat162float(hb[q]));
    }
    const size_t e4 = ((size_t)i * 128 + j) >> 2;
    ((uint2*)Hhi)[e4] = *(uint2*)hb;
    ((uint2*)Hlo)[e4] = *(uint2*)lb;
}

// ---------------- [N,128] fp32 -> [128,N] bf16 hi/lo (fused transpose+split) --------
__global__ void transpose_split(const float* __restrict__ src,
                                __nv_bfloat16* __restrict__ hi, __nv_bfloat16* __restrict__ lo)
{
    __shared__ float tile[32][33];
    const int nb = blockIdx.x << 5;
    const int cb = blockIdx.y << 5;
    const int tx = threadIdx.x, ty = threadIdx.y;
#pragma unroll
    for (int i = 0; i < 32; i += 8)
        tile[ty + i][tx] = src[(size_t)(nb + ty + i) * DIM + cb + tx];
    __syncthreads();
#pragma unroll
    for (int i = 0; i < 32; i += 8) {
        const float v = tile[tx][ty + i];
        const __nv_bfloat16 h = __float2bfloat16(v);
        const size_t idx = (size_t)(cb + ty + i) * N_NODES + nb + tx;
        hi[idx] = h;
        lo[idx] = __float2bfloat16(v - __bfloat162float(h));
    }
}

// ---------------- transpose the 6 ggnn weight matrices ----------------
__global__ void transpose_w_kernel(const float* __restrict__ w, float* __restrict__ wT)
{
    const int t = blockIdx.x * 256 + threadIdx.x;
    const int s = t >> 14;
    const int j = (t >> 7) & 127;
    const int k = t & 127;
    wT[t] = w[(s << 14) + (k << 7) + j];
}

// ---------------- BN stats ----------------
__global__ void bnstats_kernel(const float* __restrict__ T, int len,
                               float* __restrict__ mean, float* __restrict__ rstd)
{
    __shared__ double sh[256], sh2[256];
    const int c = blockIdx.x;
    const float* p = T + (size_t)c * len;
    double s = 0.0, s2 = 0.0;
    for (int i = threadIdx.x; i < len; i += 256) {
        const double v = (double)p[i];
        s += v; s2 += v * v;
    }
    sh[threadIdx.x] = s; sh2[threadIdx.x] = s2;
    __syncthreads();
    for (int st = 128; st > 0; st >>= 1) {
        if (threadIdx.x < st) {
            sh[threadIdx.x]  += sh[threadIdx.x + st];
            sh2[threadIdx.x] += sh2[threadIdx.x + st];
        }
        __syncthreads();
    }
    if (threadIdx.x == 0) {
        const double m   = sh[0] / len;
        const double var = sh2[0] / len - m * m;
        mean[c] = (float)m;
        rstd[c] = (float)(1.0 / sqrt(var + 1e-5));
    }
}

__global__ void bnstats_mask(const float* __restrict__ T,
                             float* __restrict__ mean, float* __restrict__ rstd)
{
    __shared__ double sh[256], sh2[256];
    const int c = blockIdx.x;
    const float* p = T + (size_t)c * GR * 512;
    double s = 0.0, s2 = 0.0;
    for (int i = threadIdx.x; i < GR * 512; i += 256) {
        if ((i & 511) < 510) {
            const double v = (double)p[i];
            s += v; s2 += v * v;
        }
    }
    sh[threadIdx.x] = s; sh2[threadIdx.x] = s2;
    __syncthreads();
    for (int st = 128; st > 0; st >>= 1) {
        if (threadIdx.x < st) {
            sh[threadIdx.x]  += sh[threadIdx.x + st];
            sh2[threadIdx.x] += sh2[threadIdx.x + st];
        }
        __syncthreads();
    }
    if (threadIdx.x == 0) {
        const double len = (double)(GR * 510);
        const double m   = sh[0] / len;
        const double var = sh2[0] / len - m * m;
        mean[c] = (float)m;
        rstd[c] = (float)(1.0 / sqrt(var + 1e-5));
    }
}

// ---------------- fused BN + ReLU + MaxPool ----------------
template<int PK, int PS>
__global__ void pool_f32(const float* __restrict__ T, const float* __restrict__ mean,
                         const float* __restrict__ rstd, const float* __restrict__ gamma,
                         const float* __restrict__ beta, float* __restrict__ O,
                         int LinStride, int Lpool, int total)
{
    const int idx = blockIdx.x * 256 + threadIdx.x;
    if (idx >= total) return;
    const int lp   = idx % Lpool;
    const int rest = idx / Lpool;
    const int g    = rest & 127;
    const int c    = rest >> 7;
    const float* p = T + ((size_t)c * GR + g) * LinStride + lp * PS;
    const float a = rstd[c] * gamma[c];
    const float b = beta[c] - mean[c] * a;
    float mx = 0.f;
#pragma unroll
    for (int t = 0; t < PK; t++) mx = fmaxf(mx, fmaf(p[t], a, b));
    O[idx] = mx;
}

template<int PK, int PS>
__global__ void pool_bf16(const float* __restrict__ T, const float* __restrict__ mean,
                          const float* __restrict__ rstd, const float* __restrict__ gamma,
                          const float* __restrict__ beta,
                          __nv_bfloat16* __restrict__ Ohi, __nv_bfloat16* __restrict__ Olo,
                          int LinStride, int Lpool, int total)
{
    const int idx = blockIdx.x * 256 + threadIdx.x;
    if (idx >= total) return;
    const int lp   = idx % Lpool;
    const int rest = idx / Lpool;
    const int g    = rest & 127;
    const int c    = rest >> 7;
    const float* p = T + ((size_t)c * GR + g) * LinStride + lp * PS;
    const float a = rstd[c] * gamma[c];
    const float b = beta[c] - mean[c] * a;
    float mx = 0.f;
#pragma unroll
    for (int t = 0; t < PK; t++) mx = fmaxf(mx, fmaf(p[t], a, b));
    const __nv_bfloat16 h = __float2bfloat16(mx);
    Ohi[idx] = h;
    Olo[idx] = __float2bfloat16(mx - __bfloat162float(h));
}

// ---------------- readout ----------------
__global__ void final_kernel(const float* __restrict__ P2, const float* __restrict__ Q2,
                             const float* __restrict__ wy, const float* __restrict__ by,
                             const float* __restrict__ wz, const float* __restrict__ bz,
                             float* __restrict__ out)
{
    const int g = blockIdx.x;
    __shared__ float s0[128], s1[128];
    const int l = threadIdx.x;
    float a0 = 0.f, a1 = 0.f;
    if (l < 127) {
        float y0 = by[0], y1 = by[1];
#pragma unroll 4
        for (int d = 0; d < 128; d++) {
            const float v = P2[((size_t)d * GR + g) * 127 + l];
            y0 = fmaf(v, wy[d],        y0);
            y1 = fmaf(v, wy[128 + d],  y1);
        }
        float z0 = bz[0], z1 = bz[1];
#pragma unroll 4
        for (int cc = 0; cc < 256; cc++) {
            const float v = Q2[((size_t)cc * GR + g) * 127 + l];
            z0 = fmaf(v, wz[cc],       z0);
            z1 = fmaf(v, wz[256 + cc], z1);
        }
        a0 = y0 * z0; a1 = y1 * z1;
    }
    s0[l] = a0; s1[l] = a1;
    __syncthreads();
    for (int st = 64; st > 0; st >>= 1) {
        if (l < st) { s0[l] += s0[l + st]; s1[l] += s1[l + st]; }
        __syncthreads();
    }
    if (l == 0) {
        out[g * 2 + 0] = s0[0] / 127.f;
        out[g * 2 + 1] = s1[0] / 127.f;
    }
}

// ---------------- host orchestration ----------------
extern "C" void kernel_launch(void* const* d_in, const int* in_sizes, int n_in,
                              void* d_out, int out_size)
{
    const float* x    = (const float*)d_in[0];
    const int*   ei   = (const int*)  d_in[1];
    const float* ew   = (const float*)d_in[2];
    const float* ggw  = (const float*)d_in[4];
    const float* wih  = (const float*)d_in[5];
    const float* whh  = (const float*)d_in[6];
    const float* bih  = (const float*)d_in[7];
    const float* bhh  = (const float*)d_in[8];
    const float* c1w  = (const float*)d_in[9];
    const float* c1b  = (const float*)d_in[10];
    const float* c2w  = (const float*)d_in[11];
    const float* c2b  = (const float*)d_in[12];
    const float* cc1w = (const float*)d_in[13];
    const float* cc1b = (const float*)d_in[14];
    const float* cc2w = (const float*)d_in[15];
    const float* cc2b = (const float*)d_in[16];
    const float* bn1g = (const float*)d_in[17];
    const float* bn1b = (const float*)d_in[18];
    const float* bn2g = (const float*)d_in[19];
    const float* bn2b = (const float*)d_in[20];
    const float* myw  = (const float*)d_in[21];
    const float* myb  = (const float*)d_in[22];
    const float* mzw  = (const float*)d_in[23];
    const float* mzb  = (const float*)d_in[24];
    float* out = (float*)d_out;

    float *H, *Msg, *AGG, *GX, *GH, *WT, *T1, *U1, *T2, *U2, *P2, *Q2, *MEAN, *RSTD;
    __nv_bfloat16 *Hhi, *Hlo, *Ahi, *Alo, *WThi, *WTlo, *IHhi, *IHlo, *HHhi, *HHlo;
    __nv_bfloat16 *CAThi, *CATlo, *P1hi, *P1lo, *Q1hi, *Q1lo;
    __nv_bfloat16 *CW1hi, *CW1lo, *CW2hi, *CW2lo, *CC1hi, *CC1lo, *CC2hi, *CC2lo;
    cudaGetSymbolAddress((void**)&H,   g_H);
    cudaGetSymbolAddress((void**)&Msg, g_M);
    cudaGetSymbolAddress((void**)&AGG, g_AGG);
    cudaGetSymbolAddress((void**)&GX,  g_GX);
    cudaGetSymbolAddress((void**)&GH,  g_GH);
    cudaGetSymbolAddress((void**)&WT,  g_WT);
    cudaGetSymbolAddress((void**)&T1,  g_T1);
    cudaGetSymbolAddress((void**)&U1,  g_U1);
    cudaGetSymbolAddress((void**)&T2,  g_T2);
    cudaGetSymbolAddress((void**)&U2,  g_U2);
    cudaGetSymbolAddress((void**)&P2,  g_P2);
    cudaGetSymbolAddress((void**)&Q2,  g_Q2);
    cudaGetSymbolAddress((void**)&MEAN, g_MEAN);
    cudaGetSymbolAddress((void**)&RSTD, g_RSTD);
    cudaGetSymbolAddress((void**)&Hhi, g_Hhi);
    cudaGetSymbolAddress((void**)&Hlo, g_Hlo);
    cudaGetSymbolAddress((void**)&Ahi, g_Ahi);
    cudaGetSymbolAddress((void**)&Alo, g_Alo);
    cudaGetSymbolAddress((void**)&WThi, g_WThi);
    cudaGetSymbolAddress((void**)&WTlo, g_WTlo);
    cudaGetSymbolAddress((void**)&IHhi, g_IHhi);
    cudaGetSymbolAddress((void**)&IHlo, g_IHlo);
    cudaGetSymbolAddress((void**)&HHhi, g_HHhi);
    cudaGetSymbolAddress((void**)&HHlo, g_HHlo);
    cudaGetSymbolAddress((void**)&CAThi, g_CAThi);
    cudaGetSymbolAddress((void**)&CATlo, g_CATlo);
    cudaGetSymbolAddress((void**)&P1hi, g_P1hi);
    cudaGetSymbolAddress((void**)&P1lo, g_P1lo);
    cudaGetSymbolAddress((void**)&Q1hi, g_Q1hi);
    cudaGetSymbolAddress((void**)&Q1lo, g_Q1lo);
    cudaGetSymbolAddress((void**)&CW1hi, g_CW1hi);
    cudaGetSymbolAddress((void**)&CW1lo, g_CW1lo);
    cudaGetSymbolAddress((void**)&CW2hi, g_CW2hi);
    cudaGetSymbolAddress((void**)&CW2lo, g_CW2lo);
    cudaGetSymbolAddress((void**)&CC1hi, g_CC1hi);
    cudaGetSymbolAddress((void**)&CC1lo, g_CC1lo);
    cudaGetSymbolAddress((void**)&CC2hi, g_CC2hi);
    cudaGetSymbolAddress((void**)&CC2lo, g_CC2lo);

    cudaFuncSetAttribute(gemm_mma, cudaFuncAttributeMaxDynamicSharedMemorySize, MMA_SMEM);
    cudaFuncSetAttribute(conv_mma, cudaFuncAttributeMaxDynamicSharedMemorySize, CONV_SMEM);

    const size_t ndbytes = (size_t)N_NODES * DIM * sizeof(float);

    // ---- preamble ----
    cudaMemcpyAsync(H, x, ndbytes, cudaMemcpyDeviceToDevice);
    split_kernel<<<(N_NODES * DIM / 4) / 256, 256>>>(x, Hhi, Hlo, N_NODES * DIM / 4);
    transpose_w_kernel<<<(GSTEPS * DIM * DIM) / 256, 256>>>(ggw, WT);
    split_kernel<<<(GSTEPS * DIM * DIM / 4 + 255) / 256, 256>>>(WT,  WThi, WTlo, GSTEPS * DIM * DIM / 4);
    split_kernel<<<(384 * DIM / 4 + 255) / 256, 256>>>(wih, IHhi, IHlo, 384 * DIM / 4);
    split_kernel<<<(384 * DIM / 4 + 255) / 256, 256>>>(whh, HHhi, HHlo, 384 * DIM / 4);
    convw_prep<<<(3 * 128 * 128 + 255) / 256, 256>>>(c1w,  CW1hi, CW1lo, 128, 128, 3);
    convw_prep<<<(128 * 128 + 255) / 256, 256>>>(c2w,  CW2hi, CW2lo, 128, 128, 1);
    convw_prep<<<(3 * 256 * 256 + 255) / 256, 256>>>(cc1w, CC1hi, CC1lo, 256, 256, 3);
    convw_prep<<<(256 * 256 + 255) / 256, 256>>>(cc2w, CC2hi, CC2lo, 256, 256, 1);

    // ---- GGNN loop ----
    for (int s = 0; s < GSTEPS; s++) {
        gemm_mma<<<dim3(512, 1), 256, MMA_SMEM>>>(Hhi, Hlo, WThi + s * DIM * DIM, WTlo + s * DIM * DIM,
                                                  nullptr, Msg, 128);
        cudaMemsetAsync(AGG, 0, ndbytes);
        scatter_kernel<<<(NE * 32) / 256, 256>>>(Msg, ei, ew, AGG);
        split_kernel<<<(N_NODES * DIM / 4) / 256, 256>>>(AGG, Ahi, Alo, N_NODES * DIM / 4);
        gemm_mma<<<dim3(512, 3), 256, MMA_SMEM>>>(Hhi, Hlo, HHhi, HHlo, bhh, GH, 384);
        gemm_mma<<<dim3(512, 3), 256, MMA_SMEM>>>(Ahi, Alo, IHhi, IHlo, bih, GX, 384);
        gru_kernel<<<(N_NODES * 32) / 256, 256>>>(GX, GH, H, Hhi, Hlo);
    }

    // ---- CAT (bf16 hi/lo directly, fused transpose+split) ----
    transpose_split<<<dim3(N_NODES / 32, 4), dim3(32, 8)>>>(H, CAThi, CATlo);
    transpose_split<<<dim3(N_NODES / 32, 4), dim3(32, 8)>>>(x, CAThi + (size_t)128 * N_NODES,
                                                            CATlo + (size_t)128 * N_NODES);

    // ---- branch Y ----
    conv_mma<<<dim3(512, 1), 256, CONV_SMEM>>>(CW1hi, CW1lo, CAThi, CATlo, c1b, T1, 128, 128, 3, 65536);
    bnstats_mask<<<128, 256>>>(T1, MEAN, RSTD);
    pool_bf16<3, 2><<<(128 * GR * 254) / 256, 256>>>(T1, MEAN, RSTD, bn1g, bn1b, P1hi, P1lo, 512, 254, 128 * GR * 254);
    conv_mma<<<dim3(254, 1), 256, CONV_SMEM>>>(CW2hi, CW2lo, P1hi, P1lo, c2b, T2, 128, 128, 1, 32512);
    bnstats_kernel<<<128, 256>>>(T2, 32512, MEAN, RSTD);
    pool_f32<2, 2><<<(128 * GR * 127) / 256, 256>>>(T2, MEAN, RSTD, bn1g, bn1b, P2, 254, 127, 128 * GR * 127);

    // ---- branch Z ----
    conv_mma<<<dim3(512, 2), 256, CONV_SMEM>>>(CC1hi, CC1lo, CAThi, CATlo, cc1b, U1, 256, 256, 3, 65536);
    bnstats_mask<<<256, 256>>>(U1, MEAN, RSTD);
    pool_bf16<3, 2><<<(256 * GR * 254) / 256, 256>>>(U1, MEAN, RSTD, bn2g, bn2b, Q1hi, Q1lo, 512, 254, 256 * GR * 254);
    conv_mma<<<dim3(254, 2), 256, CONV_SMEM>>>(CC2hi, CC2lo, Q1hi, Q1lo, cc2b, U2, 256, 256, 1, 32512);
    bnstats_kernel<<<256, 256>>>(U2, 32512, MEAN, RSTD);
    pool_f32<2, 2><<<(256 * GR * 127) / 256, 256>>>(U2, MEAN, RSTD, bn2g, bn2b, Q2, 254, 127, 256 * GR * 127);

    final_kernel<<<GR, 128>>>(P2, Q2, myw, myb, mzw, mzb, out);
}

// round 17
// speedup vs baseline: 1.0374x; 1.0374x over previous
#include <cuda_runtime.h>
#include <cuda_bf16.h>
#include <math.h>
#include <stdint.h>

#define N_NODES 65536
#define DIM     128
#define GR      128
#define NE      262144
#define GSTEPS  6

// ---------------- scratch ----------------
__device__ float g_H  [N_NODES * DIM];
__device__ float g_M  [N_NODES * DIM];
__device__ float g_GX [N_NODES * 384];
__device__ float g_GH [N_NODES * 384];
__device__ float g_WT [GSTEPS * DIM * DIM];
__device__ float g_T1 [128 * GR * 512];      // stride 512; l>=510 garbage (masked)
__device__ float g_U1 [256 * GR * 512];
__device__ float g_T2 [128 * GR * 254];
__device__ float g_U2 [256 * GR * 254];
__device__ float g_P2 [128 * GR * 127];
__device__ float g_Q2 [256 * GR * 127];
__device__ float g_MEAN[256];
__device__ float g_RSTD[256];
// CSR by destination (built once per call)
__device__ int   g_DEG [N_NODES];
__device__ int   g_CNT [N_NODES];
__device__ int   g_OFF [N_NODES + 1];
__device__ int   g_ESRC[NE];
__device__ float g_EWS [NE];
// bf16 split operands
__device__ __nv_bfloat16 g_Hhi [N_NODES * DIM];
__device__ __nv_bfloat16 g_Hlo [N_NODES * DIM];
__device__ __nv_bfloat16 g_Ahi [N_NODES * DIM];
__device__ __nv_bfloat16 g_Alo [N_NODES * DIM];
__device__ __nv_bfloat16 g_WThi[GSTEPS * DIM * DIM];
__device__ __nv_bfloat16 g_WTlo[GSTEPS * DIM * DIM];
__device__ __nv_bfloat16 g_IHhi[384 * DIM];
__device__ __nv_bfloat16 g_IHlo[384 * DIM];
__device__ __nv_bfloat16 g_HHhi[384 * DIM];
__device__ __nv_bfloat16 g_HHlo[384 * DIM];
__device__ __nv_bfloat16 g_CAThi[256 * N_NODES + 256];
__device__ __nv_bfloat16 g_CATlo[256 * N_NODES + 256];
__device__ __nv_bfloat16 g_P1hi[128 * GR * 254 + 256];
__device__ __nv_bfloat16 g_P1lo[128 * GR * 254 + 256];
__device__ __nv_bfloat16 g_Q1hi[256 * GR * 254 + 256];
__device__ __nv_bfloat16 g_Q1lo[256 * GR * 254 + 256];
// conv weights reordered [t][co][ci], split
__device__ __nv_bfloat16 g_CW1hi[3 * 128 * 128], g_CW1lo[3 * 128 * 128];
__device__ __nv_bfloat16 g_CW2hi[128 * 128],     g_CW2lo[128 * 128];
__device__ __nv_bfloat16 g_CC1hi[3 * 256 * 256], g_CC1lo[3 * 256 * 256];
__device__ __nv_bfloat16 g_CC2hi[256 * 256],     g_CC2lo[256 * 256];

__device__ __forceinline__ uint32_t smem_u32(const void* p) {
    uint32_t a;
    asm("{ .reg .u64 t; cvta.to.shared.u64 t, %1; cvt.u32.u64 %0, t; }" : "=r"(a) : "l"(p));
    return a;
}

#define ROWB 272
#define TILEB (128 * ROWB)

// ================= warp-level mma.sync split-bf16 GEMM (R9, measured 3293) ============
#define OFF_AHI 0
#define OFF_ALO TILEB
#define OFF_BHI (2 * TILEB)
#define OFF_BLO (3 * TILEB)
#define MMA_SMEM (4 * TILEB)

__global__ __launch_bounds__(256) void gemm_mma(
    const __nv_bfloat16* __restrict__ Ahi, const __nv_bfloat16* __restrict__ Alo,
    const __nv_bfloat16* __restrict__ Bhi, const __nv_bfloat16* __restrict__ Blo,
    const float* __restrict__ bias, float* __restrict__ C, int Ncols)
{
    extern __shared__ char sm[];
    const uint32_t sb = smem_u32(sm);
    const int tid  = threadIdx.x;
    const int wid  = tid >> 5;
    const int lane = tid & 31;

    {
        const int r    = tid & 127;
        const int kc   = (tid >> 7) << 6;
        const size_t ar = ((size_t)blockIdx.x * 128 + r) * 128 + kc;
        const size_t br = ((size_t)blockIdx.y * 128 + r) * 128 + kc;
        char* dst = sm + r * ROWB + kc * 2;
#pragma unroll
        for (int kk = 0; kk < 64; kk += 8) {
            *(uint4*)(dst + OFF_AHI + kk * 2) = *(const uint4*)(Ahi + ar + kk);
            *(uint4*)(dst + OFF_ALO + kk * 2) = *(const uint4*)(Alo + ar + kk);
            *(uint4*)(dst + OFF_BHI + kk * 2) = *(const uint4*)(Bhi + br + kk);
            *(uint4*)(dst + OFF_BLO + kk * 2) = *(const uint4*)(Blo + br + kk);
        }
    }
    __syncthreads();

    const int warpM = (wid >> 2) * 64;
    const int warpN = (wid & 3) * 32;

    float acc[4][4][4];
#pragma unroll
    for (int i = 0; i < 4; i++)
#pragma unroll
        for (int j = 0; j < 4; j++)
#pragma unroll
            for (int k = 0; k < 4; k++) acc[i][j][k] = 0.f;

    const uint32_t aoff[3] = {OFF_AHI, OFF_AHI, OFF_ALO};
    const uint32_t boff[3] = {OFF_BHI, OFF_BLO, OFF_BHI};

    const uint32_t a_r = warpM + (lane & 15);
    const uint32_t a_k = (lane >> 4) * 8;
    const uint32_t b_r = warpN + (lane & 7);
    const uint32_t b_k = ((lane >> 3) & 1) * 8;

#pragma unroll
    for (int s = 0; s < 3; s++) {
        const uint32_t ab = sb + aoff[s];
        const uint32_t bb = sb + boff[s];
#pragma unroll
        for (int ks = 0; ks < 8; ks++) {
            uint32_t a[4][4], b[4][2];
#pragma unroll
            for (int mi = 0; mi < 4; mi++) {
                const uint32_t addr = ab + (a_r + mi * 16) * ROWB + (ks * 16 + a_k) * 2;
                asm volatile("ldmatrix.sync.aligned.m8n8.x4.shared.b16 {%0,%1,%2,%3}, [%4];"
                             : "=r"(a[mi][0]), "=r"(a[mi][1]), "=r"(a[mi][2]), "=r"(a[mi][3])
                             : "r"(addr));
            }
#pragma unroll
            for (int ni = 0; ni < 4; ni++) {
                const uint32_t addr = bb + (b_r + ni * 8) * ROWB + (ks * 16 + b_k) * 2;
                asm volatile("ldmatrix.sync.aligned.m8n8.x2.shared.b16 {%0,%1}, [%2];"
                             : "=r"(b[ni][0]), "=r"(b[ni][1]) : "r"(addr));
            }
#pragma unroll
            for (int mi = 0; mi < 4; mi++)
#pragma unroll
                for (int ni = 0; ni < 4; ni++) {
                    asm volatile(
                        "mma.sync.aligned.m16n8k16.row.col.f32.bf16.bf16.f32 "
                        "{%0,%1,%2,%3}, {%4,%5,%6,%7}, {%8,%9}, {%0,%1,%2,%3};"
                        : "+f"(acc[mi][ni][0]), "+f"(acc[mi][ni][1]),
                          "+f"(acc[mi][ni][2]), "+f"(acc[mi][ni][3])
                        : "r"(a[mi][0]), "r"(a[mi][1]), "r"(a[mi][2]), "r"(a[mi][3]),
                          "r"(b[ni][0]), "r"(b[ni][1]));
                }
        }
    }

    const int rbase = blockIdx.x * 128 + warpM + (lane >> 2);
    const int cbase = blockIdx.y * 128 + warpN + 2 * (lane & 3);
#pragma unroll
    for (int mi = 0; mi < 4; mi++) {
#pragma unroll
        for (int ni = 0; ni < 4; ni++) {
            const int row = rbase + mi * 16;
            const int col = cbase + ni * 8;
            float b0 = 0.f, b1 = 0.f;
            if (bias) { b0 = bias[col]; b1 = bias[col + 1]; }
            *(float2*)(C + (size_t)row * Ncols + col) =
                make_float2(acc[mi][ni][0] + b0, acc[mi][ni][1] + b1);
            *(float2*)(C + (size_t)(row + 8) * Ncols + col) =
                make_float2(acc[mi][ni][2] + b0, acc[mi][ni][3] + b1);
        }
    }
}

// ================= conv as split-bf16 mma GEMM (R9, measured 3293) ================
#define CB_ROWS 130
#define CBTILE (CB_ROWS * ROWB)
#define C_AHI 0
#define C_ALO TILEB
#define C_BHI (2 * TILEB)
#define C_BLO (2 * TILEB + CBTILE)
#define CONV_SMEM (2 * TILEB + 2 * CBTILE)

__global__ __launch_bounds__(256) void conv_mma(
    const __nv_bfloat16* __restrict__ Whi, const __nv_bfloat16* __restrict__ Wlo,
    const __nv_bfloat16* __restrict__ Xhi, const __nv_bfloat16* __restrict__ Xlo,
    const float* __restrict__ bias, float* __restrict__ C,
    int Cout, int Cin, int KW, int NS)
{
    extern __shared__ char sm[];
    const uint32_t sb = smem_u32(sm);
    const int tid  = threadIdx.x;
    const int wid  = tid >> 5;
    const int lane = tid & 31;
    const int n0   = blockIdx.x * 128;
    const int cob  = blockIdx.y * 128;

    const int warpM = (wid >> 2) * 64;
    const int warpN = (wid & 3) * 32;

    float acc[4][4][4];
#pragma unroll
    for (int i = 0; i < 4; i++)
#pragma unroll
        for (int j = 0; j < 4; j++)
#pragma unroll
            for (int k = 0; k < 4; k++) acc[i][j][k] = 0.f;

    const uint32_t a_r = warpM + (lane & 15);
    const uint32_t a_k = (lane >> 4) * 8;
    const uint32_t b_r = warpN + (lane & 7);
    const uint32_t b_k = ((lane >> 3) & 1) * 8;

    const int nkc = Cin >> 7;
    for (int kc = 0; kc < nkc; kc++) {
        const int ci0 = kc << 7;
        __syncthreads();
        {
            const int nn  = tid & 127;
            const int kst = tid >> 7;
            const __nv_bfloat16* ph = Xhi + (size_t)(ci0 + kst) * NS + n0 + nn;
            const __nv_bfloat16* pl = Xlo + (size_t)(ci0 + kst) * NS + n0 + nn;
            char* dh = sm + C_BHI + nn * ROWB + kst * 2;
            char* dl = sm + C_BLO + nn * ROWB + kst * 2;
#pragma unroll 8
            for (int j = 0; j < 64; j++) {
                *(__nv_bfloat16*)dh = *ph;
                *(__nv_bfloat16*)dl = *pl;
                ph += 2 * (size_t)NS; pl += 2 * (size_t)NS;
                dh += 4; dl += 4;
            }
            const int k2 = tid & 127;
            const int re = 128 + (tid >> 7);
            *(__nv_bfloat16*)(sm + C_BHI + re * ROWB + k2 * 2) = Xhi[(size_t)(ci0 + k2) * NS + n0 + re];
            *(__nv_bfloat16*)(sm + C_BLO + re * ROWB + k2 * 2) = Xlo[(size_t)(ci0 + k2) * NS + n0 + re];
        }
        for (int t = 0; t < KW; t++) {
            __syncthreads();
            {
                const int r  = tid & 127;
                const int kh = (tid >> 7) << 6;
                const size_t src = ((size_t)(t * Cout + cob + r)) * Cin + ci0 + kh;
                char* da = sm + C_AHI + r * ROWB + kh * 2;
                char* dl = sm + C_ALO + r * ROWB + kh * 2;
#pragma unroll
                for (int kk = 0; kk < 64; kk += 8) {
                    *(uint4*)(da + kk * 2) = *(const uint4*)(Whi + src + kk);
                    *(uint4*)(dl + kk * 2) = *(const uint4*)(Wlo + src + kk);
                }
            }
            __syncthreads();
            const uint32_t aoffs[3] = {C_AHI, C_AHI, C_ALO};
            const uint32_t boffs[3] = {C_BHI, C_BLO, C_BHI};
#pragma unroll
            for (int s = 0; s < 3; s++) {
                const uint32_t ab = sb + aoffs[s];
                const uint32_t bb = sb + boffs[s] + (uint32_t)t * ROWB;
#pragma unroll
                for (int ks = 0; ks < 8; ks++) {
                    uint32_t a[4][4], b[4][2];
#pragma unroll
                    for (int mi = 0; mi < 4; mi++) {
                        const uint32_t addr = ab + (a_r + mi * 16) * ROWB + (ks * 16 + a_k) * 2;
                        asm volatile("ldmatrix.sync.aligned.m8n8.x4.shared.b16 {%0,%1,%2,%3}, [%4];"
                                     : "=r"(a[mi][0]), "=r"(a[mi][1]), "=r"(a[mi][2]), "=r"(a[mi][3])
                                     : "r"(addr));
                    }
#pragma unroll
                    for (int ni = 0; ni < 4; ni++) {
                        const uint32_t addr = bb + (b_r + ni * 8) * ROWB + (ks * 16 + b_k) * 2;
                        asm volatile("ldmatrix.sync.aligned.m8n8.x2.shared.b16 {%0,%1}, [%2];"
                                     : "=r"(b[ni][0]), "=r"(b[ni][1]) : "r"(addr));
                    }
#pragma unroll
                    for (int mi = 0; mi < 4; mi++)
#pragma unroll
                        for (int ni = 0; ni < 4; ni++) {
                            asm volatile(
                                "mma.sync.aligned.m16n8k16.row.col.f32.bf16.bf16.f32 "
                                "{%0,%1,%2,%3}, {%4,%5,%6,%7}, {%8,%9}, {%0,%1,%2,%3};"
                                : "+f"(acc[mi][ni][0]), "+f"(acc[mi][ni][1]),
                                  "+f"(acc[mi][ni][2]), "+f"(acc[mi][ni][3])
                                : "r"(a[mi][0]), "r"(a[mi][1]), "r"(a[mi][2]), "r"(a[mi][3]),
                                  "r"(b[ni][0]), "r"(b[ni][1]));
                        }
                }
            }
        }
    }

    const int rb  = cob + warpM + (lane >> 2);
    const int cb2 = n0 + warpN + 2 * (lane & 3);
#pragma unroll
    for (int mi = 0; mi < 4; mi++) {
#pragma unroll
        for (int ni = 0; ni < 4; ni++) {
            const int row = rb + mi * 16;
            const int col = cb2 + ni * 8;
            const float b0 = bias[row];
            const float b1 = bias[row + 8];
            *(float2*)(C + (size_t)row * NS + col) =
                make_float2(acc[mi][ni][0] + b0, acc[mi][ni][1] + b0);
            *(float2*)(C + (size_t)(row + 8) * NS + col) =
                make_float2(acc[mi][ni][2] + b1, acc[mi][ni][3] + b1);
        }
    }
}

// ================= CSR build (once per call) =================
__global__ void hist_kernel(const int* __restrict__ ei, int* __restrict__ DEG)
{
    const int e = blockIdx.x * 256 + threadIdx.x;
    if (e < NE) atomicAdd(&DEG[ei[NE + e]], 1);
}

// single-block scan: 256 threads x 256 elements (low register pressure)
__global__ __launch_bounds__(256) void scan_kernel(const int* __restrict__ DEG, int* __restrict__ OFF)
{
    __shared__ int part[256];
    const int tid  = threadIdx.x;
    const int base = tid * 256;
    int s = 0;
    for (int i = 0; i < 256; i++) s += DEG[base + i];
    part[tid] = s;
    __syncthreads();
    // Hillis-Steele inclusive scan over 256 partials
    for (int off = 1; off < 256; off <<= 1) {
        int v = (tid >= off) ? part[tid - off] : 0;
        __syncthreads();
        part[tid] += v;
        __syncthreads();
    }
    int run = (tid > 0) ? part[tid - 1] : 0;
    for (int i = 0; i < 256; i++) {
        OFF[base + i] = run;
        run += DEG[base + i];
    }
    if (tid == 255) OFF[N_NODES] = run;
}

__global__ void fill_kernel(const int* __restrict__ ei, const float* __restrict__ ew,
                            const int* __restrict__ OFF, int* __restrict__ CNT,
                            int* __restrict__ ESRC, float* __restrict__ EWS)
{
    const int e = blockIdx.x * 256 + threadIdx.x;
    if (e >= NE) return;
    const int d = ei[NE + e];
    const int pos = atomicAdd(&CNT[d], 1);
    const int idx = OFF[d] + pos;
    ESRC[idx] = ei[e];
    EWS[idx]  = ew[e];
}

// ---- pull-mode aggregation: agg[n] = sum_e w_e * Msg[src_e]; write bf16 hi/lo ----
__global__ void gather_kernel(const float* __restrict__ Msg, const int* __restrict__ ESRC,
                              const float* __restrict__ EWS, const int* __restrict__ OFF,
                              __nv_bfloat16* __restrict__ Ahi, __nv_bfloat16* __restrict__ Alo)
{
    const int n    = blockIdx.x * 8 + (threadIdx.x >> 5);
    const int lane = threadIdx.x & 31;
    const int beg = OFF[n], end = OFF[n + 1];
    float4 acc = make_float4(0.f, 0.f, 0.f, 0.f);
    for (int p = beg; p < end; p++) {
        const int   s = ESRC[p];
        const float w = EWS[p];
        const float4 v = *(const float4*)(Msg + (size_t)s * DIM + lane * 4);
        acc.x = fmaf(w, v.x, acc.x);
        acc.y = fmaf(w, v.y, acc.y);
        acc.z = fmaf(w, v.z, acc.z);
        acc.w = fmaf(w, v.w, acc.w);
    }
    float fs[4] = {acc.x, acc.y, acc.z, acc.w};
    __nv_bfloat16 hb[4], lb[4];
#pragma unroll
    for (int q = 0; q < 4; q++) {
        hb[q] = __float2bfloat16(fs[q]);
        lb[q] = __float2bfloat16(fs[q] - __bfloat162float(hb[q]));
    }
    const size_t e4 = ((size_t)n * DIM + lane * 4) >> 2;
    ((uint2*)Ahi)[e4] = *(uint2*)hb;
    ((uint2*)Alo)[e4] = *(uint2*)lb;
}

// ---------------- fp32 -> (bf16 hi, bf16 lo) split ----------------
__global__ void split_kernel(const float* __restrict__ X, __nv_bfloat16* __restrict__ hi,
                             __nv_bfloat16* __restrict__ lo, int n4)
{
    const int i = blockIdx.x * 256 + threadIdx.x;
    if (i >= n4) return;
    const float4 v = ((const float4*)X)[i];
    float fs[4] = {v.x, v.y, v.z, v.w};
    __nv_bfloat16 hb[4], lb[4];
#pragma unroll
    for (int j = 0; j < 4; j++) {
        hb[j] = __float2bfloat16(fs[j]);
        lb[j] = __float2bfloat16(fs[j] - __bfloat162float(hb[j]));
    }
    ((uint2*)hi)[i] = *(uint2*)hb;
    ((uint2*)lo)[i] = *(uint2*)lb;
}

// ---------------- conv weight reorder+split ----------------
__global__ void convw_prep(const float* __restrict__ w, __nv_bfloat16* __restrict__ hi,
                           __nv_bfloat16* __restrict__ lo, int Cout, int Cin, int KW)
{
    const int idx = blockIdx.x * 256 + threadIdx.x;
    if (idx >= KW * Cout * Cin) return;
    const int ci = idx % Cin;
    const int co = (idx / Cin) % Cout;
    const int t  = idx / (Cin * Cout);
    const float v = w[((size_t)co * Cin + ci) * KW + t];
    const __nv_bfloat16 h = __float2bfloat16(v);
    hi[idx] = h;
    lo[idx] = __float2bfloat16(v - __bfloat162float(h));
}

__device__ __forceinline__ float fast_sigmoid(float v)
{
    v = fminf(fmaxf(v, -30.f), 30.f);
    return 1.f / (1.f + __expf(-v));
}
__device__ __forceinline__ float fast_tanh(float v)
{
    v = fminf(fmaxf(v, -15.f), 15.f);
    const float e = __expf(-2.f * v);
    return (1.f - e) / (1.f + e);
}

// ---------------- GRU update, fused bf16 split output ----------------
__global__ void gru_kernel(const float* __restrict__ GX, const float* __restrict__ GH,
                           float* __restrict__ H, __nv_bfloat16* __restrict__ Hhi,
                           __nv_bfloat16* __restrict__ Hlo)
{
    const int t = blockIdx.x * blockDim.x + threadIdx.x;
    const int i = t >> 5;
    const int j = (t & 31) << 2;
    const float* px = GX + (size_t)i * 384 + j;
    const float* ph = GH + (size_t)i * 384 + j;
    const float4 xr = *(const float4*)(px);
    const float4 xz = *(const float4*)(px + 128);
    const float4 xn = *(const float4*)(px + 256);
    const float4 hr = *(const float4*)(ph);
    const float4 hz = *(const float4*)(ph + 128);
    const float4 hn = *(const float4*)(ph + 256);
    float4* hp = (float4*)(H + (size_t)i * 128 + j);
    float4 h = *hp;
    float4 o;
    { const float r = fast_sigmoid(xr.x + hr.x), z = fast_sigmoid(xz.x + hz.x);
      const float n = fast_tanh(xn.x + r * hn.x); o.x = (1.f - z) * n + z * h.x; }
    { const float r = fast_sigmoid(xr.y + hr.y), z = fast_sigmoid(xz.y + hz.y);
      const float n = fast_tanh(xn.y + r * hn.y); o.y = (1.f - z) * n + z * h.y; }
    { const float r = fast_sigmoid(xr.z + hr.z), z = fast_sigmoid(xz.z + hz.z);
      const float n = fast_tanh(xn.z + r * hn.z); o.z = (1.f - z) * n + z * h.z; }
    { const float r = fast_sigmoid(xr.w + hr.w), z = fast_sigmoid(xz.w + hz.w);
      const float n = fast_tanh(xn.w + r * hn.w); o.w = (1.f - z) * n + z * h.w; }
    *hp = o;
    float fs[4] = {o.x, o.y, o.z, o.w};
    __nv_bfloat16 hb[4], lb[4];
#pragma unroll
    for (int q = 0; q < 4; q++) {
        hb[q] = __float2bfloat16(fs[q]);
        lb[q] = __float2bfloat16(fs[q] - __bfloat162float(hb[q]));
    }
    const size_t e4 = ((size_t)i * 128 + j) >> 2;
    ((uint2*)Hhi)[e4] = *(uint2*)hb;
    ((uint2*)Hlo)[e4] = *(uint2*)lb;
}

// ---------------- [N,128] fp32 -> [128,N] bf16 hi/lo (fused transpose+split) --------
__global__ void transpose_split(const float* __restrict__ src,
                                __nv_bfloat16* __restrict__ hi, __nv_bfloat16* __restrict__ lo)
{
    __shared__ float tile[32][33];
    const int nb = blockIdx.x << 5;
    const int cb = blockIdx.y << 5;
    const int tx = threadIdx.x, ty = threadIdx.y;
#pragma unroll
    for (int i = 0; i < 32; i += 8)
        tile[ty + i][tx] = src[(size_t)(nb + ty + i) * DIM + cb + tx];
    __syncthreads();
#pragma unroll
    for (int i = 0; i < 32; i += 8) {
        const float v = tile[tx][ty + i];
        const __nv_bfloat16 h = __float2bfloat16(v);
        const size_t idx = (size_t)(cb + ty + i) * N_NODES + nb + tx;
        hi[idx] = h;
        lo[idx] = __float2bfloat16(v - __bfloat162float(h));
    }
}

// ---------------- transpose the 6 ggnn weight matrices ----------------
__global__ void transpose_w_kernel(const float* __restrict__ w, float* __restrict__ wT)
{
    const int t = blockIdx.x * 256 + threadIdx.x;
    const int s = t >> 14;
    const int j = (t >> 7) & 127;
    const int k = t & 127;
    wT[t] = w[(s << 14) + (k << 7) + j];
}

// ---------------- BN stats ----------------
__global__ void bnstats_kernel(const float* __restrict__ T, int len,
                               float* __restrict__ mean, float* __restrict__ rstd)
{
    __shared__ double sh[256], sh2[256];
    const int c = blockIdx.x;
    const float* p = T + (size_t)c * len;
    double s = 0.0, s2 = 0.0;
    for (int i = threadIdx.x; i < len; i += 256) {
        const double v = (double)p[i];
        s += v; s2 += v * v;
    }
    sh[threadIdx.x] = s; sh2[threadIdx.x] = s2;
    __syncthreads();
    for (int st = 128; st > 0; st >>= 1) {
        if (threadIdx.x < st) {
            sh[threadIdx.x]  += sh[threadIdx.x + st];
            sh2[threadIdx.x] += sh2[threadIdx.x + st];
        }
        __syncthreads();
    }
    if (threadIdx.x == 0) {
        const double m   = sh[0] / len;
        const double var = sh2[0] / len - m * m;
        mean[c] = (float)m;
        rstd[c] = (float)(1.0 / sqrt(var + 1e-5));
    }
}

__global__ void bnstats_mask(const float* __restrict__ T,
                             float* __restrict__ mean, float* __restrict__ rstd)
{
    __shared__ double sh[256], sh2[256];
    const int c = blockIdx.x;
    const float* p = T + (size_t)c * GR * 512;
    double s = 0.0, s2 = 0.0;
    for (int i = threadIdx.x; i < GR * 512; i += 256) {
        if ((i & 511) < 510) {
            const double v = (double)p[i];
            s += v; s2 += v * v;
        }
    }
    sh[threadIdx.x] = s; sh2[threadIdx.x] = s2;
    __syncthreads();
    for (int st = 128; st > 0; st >>= 1) {
        if (threadIdx.x < st) {
            sh[threadIdx.x]  += sh[threadIdx.x + st];
            sh2[threadIdx.x] += sh2[threadIdx.x + st];
        }
        __syncthreads();
    }
    if (threadIdx.x == 0) {
        const double len = (double)(GR * 510);
        const double m   = sh[0] / len;
        const double var = sh2[0] / len - m * m;
        mean[c] = (float)m;
        rstd[c] = (float)(1.0 / sqrt(var + 1e-5));
    }
}

// ---------------- fused BN + ReLU + MaxPool ----------------
template<int PK, int PS>
__global__ void pool_f32(const float* __restrict__ T, const float* __restrict__ mean,
                         const float* __restrict__ rstd, const float* __restrict__ gamma,
                         const float* __restrict__ beta, float* __restrict__ O,
                         int LinStride, int Lpool, int total)
{
    const int idx = blockIdx.x * 256 + threadIdx.x;
    if (idx >= total) return;
    const int lp   = idx % Lpool;
    const int rest = idx / Lpool;
    const int g    = rest & 127;
    const int c    = rest >> 7;
    const float* p = T + ((size_t)c * GR + g) * LinStride + lp * PS;
    const float a = rstd[c] * gamma[c];
    const float b = beta[c] - mean[c] * a;
    float mx = 0.f;
#pragma unroll
    for (int t = 0; t < PK; t++) mx = fmaxf(mx, fmaf(p[t], a, b));
    O[idx] = mx;
}

template<int PK, int PS>
__global__ void pool_bf16(const float* __restrict__ T, const float* __restrict__ mean,
                          const float* __restrict__ rstd, const float* __restrict__ gamma,
                          const float* __restrict__ beta,
                          __nv_bfloat16* __restrict__ Ohi, __nv_bfloat16* __restrict__ Olo,
                          int LinStride, int Lpool, int total)
{
    const int idx = blockIdx.x * 256 + threadIdx.x;
    if (idx >= total) return;
    const int lp   = idx % Lpool;
    const int rest = idx / Lpool;
    const int g    = rest & 127;
    const int c    = rest >> 7;
    const float* p = T + ((size_t)c * GR + g) * LinStride + lp * PS;
    const float a = rstd[c] * gamma[c];
    const float b = beta[c] - mean[c] * a;
    float mx = 0.f;
#pragma unroll
    for (int t = 0; t < PK; t++) mx = fmaxf(mx, fmaf(p[t], a, b));
    const __nv_bfloat16 h = __float2bfloat16(mx);
    Ohi[idx] = h;
    Olo[idx] = __float2bfloat16(mx - __bfloat162float(h));
}

// ---------------- readout ----------------
__global__ void final_kernel(const float* __restrict__ P2, const float* __restrict__ Q2,
                             const float* __restrict__ wy, const float* __restrict__ by,
                             const float* __restrict__ wz, const float* __restrict__ bz,
                             float* __restrict__ out)
{
    const int g = blockIdx.x;
    __shared__ float s0[128], s1[128];
    const int l = threadIdx.x;
    float a0 = 0.f, a1 = 0.f;
    if (l < 127) {
        float y0 = by[0], y1 = by[1];
#pragma unroll 4
        for (int d = 0; d < 128; d++) {
            const float v = P2[((size_t)d * GR + g) * 127 + l];
            y0 = fmaf(v, wy[d],        y0);
            y1 = fmaf(v, wy[128 + d],  y1);
        }
        float z0 = bz[0], z1 = bz[1];
#pragma unroll 4
        for (int cc = 0; cc < 256; cc++) {
            const float v = Q2[((size_t)cc * GR + g) * 127 + l];
            z0 = fmaf(v, wz[cc],       z0);
            z1 = fmaf(v, wz[256 + cc], z1);
        }
        a0 = y0 * z0; a1 = y1 * z1;
    }
    s0[l] = a0; s1[l] = a1;
    __syncthreads();
    for (int st = 64; st > 0; st >>= 1) {
        if (l < st) { s0[l] += s0[l + st]; s1[l] += s1[l + st]; }
        __syncthreads();
    }
    if (l == 0) {
        out[g * 2 + 0] = s0[0] / 127.f;
        out[g * 2 + 1] = s1[0] / 127.f;
    }
}

// ---------------- host orchestration ----------------
extern "C" void kernel_launch(void* const* d_in, const int* in_sizes, int n_in,
                              void* d_out, int out_size)
{
    const float* x    = (const float*)d_in[0];
    const int*   ei   = (const int*)  d_in[1];
    const float* ew   = (const float*)d_in[2];
    const float* ggw  = (const float*)d_in[4];
    const float* wih  = (const float*)d_in[5];
    const float* whh  = (const float*)d_in[6];
    const float* bih  = (const float*)d_in[7];
    const float* bhh  = (const float*)d_in[8];
    const float* c1w  = (const float*)d_in[9];
    const float* c1b  = (const float*)d_in[10];
    const float* c2w  = (const float*)d_in[11];
    const float* c2b  = (const float*)d_in[12];
    const float* cc1w = (const float*)d_in[13];
    const float* cc1b = (const float*)d_in[14];
    const float* cc2w = (const float*)d_in[15];
    const float* cc2b = (const float*)d_in[16];
    const float* bn1g = (const float*)d_in[17];
    const float* bn1b = (const float*)d_in[18];
    const float* bn2g = (const float*)d_in[19];
    const float* bn2b = (const float*)d_in[20];
    const float* myw  = (const float*)d_in[21];
    const float* myb  = (const float*)d_in[22];
    const float* mzw  = (const float*)d_in[23];
    const float* mzb  = (const float*)d_in[24];
    float* out = (float*)d_out;

    float *H, *Msg, *GX, *GH, *WT, *T1, *U1, *T2, *U2, *P2, *Q2, *MEAN, *RSTD, *EWS;
    int *DEG, *CNT, *OFF, *ESRC;
    __nv_bfloat16 *Hhi, *Hlo, *Ahi, *Alo, *WThi, *WTlo, *IHhi, *IHlo, *HHhi, *HHlo;
    __nv_bfloat16 *CAThi, *CATlo, *P1hi, *P1lo, *Q1hi, *Q1lo;
    __nv_bfloat16 *CW1hi, *CW1lo, *CW2hi, *CW2lo, *CC1hi, *CC1lo, *CC2hi, *CC2lo;
    cudaGetSymbolAddress((void**)&H,   g_H);
    cudaGetSymbolAddress((void**)&Msg, g_M);
    cudaGetSymbolAddress((void**)&GX,  g_GX);
    cudaGetSymbolAddress((void**)&GH,  g_GH);
    cudaGetSymbolAddress((void**)&WT,  g_WT);
    cudaGetSymbolAddress((void**)&T1,  g_T1);
    cudaGetSymbolAddress((void**)&U1,  g_U1);
    cudaGetSymbolAddress((void**)&T2,  g_T2);
    cudaGetSymbolAddress((void**)&U2,  g_U2);
    cudaGetSymbolAddress((void**)&P2,  g_P2);
    cudaGetSymbolAddress((void**)&Q2,  g_Q2);
    cudaGetSymbolAddress((void**)&MEAN, g_MEAN);
    cudaGetSymbolAddress((void**)&RSTD, g_RSTD);
    cudaGetSymbolAddress((void**)&DEG,  g_DEG);
    cudaGetSymbolAddress((void**)&CNT,  g_CNT);
    cudaGetSymbolAddress((void**)&OFF,  g_OFF);
    cudaGetSymbolAddress((void**)&ESRC, g_ESRC);
    cudaGetSymbolAddress((void**)&EWS,  g_EWS);
    cudaGetSymbolAddress((void**)&Hhi, g_Hhi);
    cudaGetSymbolAddress((void**)&Hlo, g_Hlo);
    cudaGetSymbolAddress((void**)&Ahi, g_Ahi);
    cudaGetSymbolAddress((void**)&Alo, g_Alo);
    cudaGetSymbolAddress((void**)&WThi, g_WThi);
    cudaGetSymbolAddress((void**)&WTlo, g_WTlo);
    cudaGetSymbolAddress((void**)&IHhi, g_IHhi);
    cudaGetSymbolAddress((void**)&IHlo, g_IHlo);
    cudaGetSymbolAddress((void**)&HHhi, g_HHhi);
    cudaGetSymbolAddress((void**)&HHlo, g_HHlo);
    cudaGetSymbolAddress((void**)&CAThi, g_CAThi);
    cudaGetSymbolAddress((void**)&CATlo, g_CATlo);
    cudaGetSymbolAddress((void**)&P1hi, g_P1hi);
    cudaGetSymbolAddress((void**)&P1lo, g_P1lo);
    cudaGetSymbolAddress((void**)&Q1hi, g_Q1hi);
    cudaGetSymbolAddress((void**)&Q1lo, g_Q1lo);
    cudaGetSymbolAddress((void**)&CW1hi, g_CW1hi);
    cudaGetSymbolAddress((void**)&CW1lo, g_CW1lo);
    cudaGetSymbolAddress((void**)&CW2hi, g_CW2hi);
    cudaGetSymbolAddress((void**)&CW2lo, g_CW2lo);
    cudaGetSymbolAddress((void**)&CC1hi, g_CC1hi);
    cudaGetSymbolAddress((void**)&CC1lo, g_CC1lo);
    cudaGetSymbolAddress((void**)&CC2hi, g_CC2hi);
    cudaGetSymbolAddress((void**)&CC2lo, g_CC2lo);

    cudaFuncSetAttribute(gemm_mma, cudaFuncAttributeMaxDynamicSharedMemorySize, MMA_SMEM);
    cudaFuncSetAttribute(conv_mma, cudaFuncAttributeMaxDynamicSharedMemorySize, CONV_SMEM);

    const size_t ndbytes = (size_t)N_NODES * DIM * sizeof(float);

    // ---- preamble: h0 = x, weight prep, CSR build ----
    cudaMemcpyAsync(H, x, ndbytes, cudaMemcpyDeviceToDevice);
    split_kernel<<<(N_NODES * DIM / 4) / 256, 256>>>(x, Hhi, Hlo, N_NODES * DIM / 4);
    transpose_w_kernel<<<(GSTEPS * DIM * DIM) / 256, 256>>>(ggw, WT);
    split_kernel<<<(GSTEPS * DIM * DIM / 4 + 255) / 256, 256>>>(WT,  WThi, WTlo, GSTEPS * DIM * DIM / 4);
    split_kernel<<<(384 * DIM / 4 + 255) / 256, 256>>>(wih, IHhi, IHlo, 384 * DIM / 4);
    split_kernel<<<(384 * DIM / 4 + 255) / 256, 256>>>(whh, HHhi, HHlo, 384 * DIM / 4);
    convw_prep<<<(3 * 128 * 128 + 255) / 256, 256>>>(c1w,  CW1hi, CW1lo, 128, 128, 3);
    convw_prep<<<(128 * 128 + 255) / 256, 256>>>(c2w,  CW2hi, CW2lo, 128, 128, 1);
    convw_prep<<<(3 * 256 * 256 + 255) / 256, 256>>>(cc1w, CC1hi, CC1lo, 256, 256, 3);
    convw_prep<<<(256 * 256 + 255) / 256, 256>>>(cc2w, CC2hi, CC2lo, 256, 256, 1);

    cudaMemsetAsync(DEG, 0, N_NODES * sizeof(int));
    cudaMemsetAsync(CNT, 0, N_NODES * sizeof(int));
    hist_kernel<<<NE / 256, 256>>>(ei, DEG);
    scan_kernel<<<1, 256>>>(DEG, OFF);
    fill_kernel<<<NE / 256, 256>>>(ei, ew, OFF, CNT, ESRC, EWS);

    // ---- GGNN loop ----
    for (int s = 0; s < GSTEPS; s++) {
        gemm_mma<<<dim3(512, 1), 256, MMA_SMEM>>>(Hhi, Hlo, WThi + s * DIM * DIM, WTlo + s * DIM * DIM,
                                                  nullptr, Msg, 128);
        gather_kernel<<<N_NODES / 8, 256>>>(Msg, ESRC, EWS, OFF, Ahi, Alo);
        gemm_mma<<<dim3(512, 3), 256, MMA_SMEM>>>(Hhi, Hlo, HHhi, HHlo, bhh, GH, 384);
        gemm_mma<<<dim3(512, 3), 256, MMA_SMEM>>>(Ahi, Alo, IHhi, IHlo, bih, GX, 384);
        gru_kernel<<<(N_NODES * 32) / 256, 256>>>(GX, GH, H, Hhi, Hlo);
    }

    // ---- CAT (bf16 hi/lo directly, fused transpose+split) ----
    transpose_split<<<dim3(N_NODES / 32, 4), dim3(32, 8)>>>(H, CAThi, CATlo);
    transpose_split<<<dim3(N_NODES / 32, 4), dim3(32, 8)>>>(x, CAThi + (size_t)128 * N_NODES,
                                                            CATlo + (size_t)128 * N_NODES);

    // ---- branch Y ----
    conv_mma<<<dim3(512, 1), 256, CONV_SMEM>>>(CW1hi, CW1lo, CAThi, CATlo, c1b, T1, 128, 128, 3, 65536);
    bnstats_mask<<<128, 256>>>(T1, MEAN, RSTD);
    pool_bf16<3, 2><<<(128 * GR * 254) / 256, 256>>>(T1, MEAN, RSTD, bn1g, bn1b, P1hi, P1lo, 512, 254, 128 * GR * 254);
    conv_mma<<<dim3(254, 1), 256, CONV_SMEM>>>(CW2hi, CW2lo, P1hi, P1lo, c2b, T2, 128, 128, 1, 32512);
    bnstats_kernel<<<128, 256>>>(T2, 32512, MEAN, RSTD);
    pool_f32<2, 2><<<(128 * GR * 127) / 256, 256>>>(T2, MEAN, RSTD, bn1g, bn1b, P2, 254, 127, 128 * GR * 127);

    // ---- branch Z ----
    conv_mma<<<dim3(512, 2), 256, CONV_SMEM>>>(CC1hi, CC1lo, CAThi, CATlo, cc1b, U1, 256, 256, 3, 65536);
    bnstats_mask<<<256, 256>>>(U1, MEAN, RSTD);
    pool_bf16<3, 2><<<(256 * GR * 254) / 256, 256>>>(U1, MEAN, RSTD, bn2g, bn2b, Q1hi, Q1lo, 512, 254, 256 * GR * 254);
    conv_mma<<<dim3(254, 2), 256, CONV_SMEM>>>(CC2hi, CC2lo, Q1hi, Q1lo, cc2b, U2, 256, 256, 1, 32512);
    bnstats_kernel<<<256, 256>>>(U2, 32512, MEAN, RSTD);
    pool_f32<2, 2><<<(256 * GR * 127) / 256, 256>>>(U2, MEAN, RSTD, bn2g, bn2b, Q2, 254, 127, 256 * GR * 127);

    final_kernel<<<GR, 128>>>(P2, Q2, myw, myb, mzw, mzb, out);
}